// round 1
// baseline (speedup 1.0000x reference)
#include <cuda_runtime.h>
#include <math.h>

#define BATCH 16
#define CH 64
#define HLO 80
#define WLO 80
#define HWLO (HLO*WLO)
#define HHI 160
#define WHI 160

// Scratch (allowed as __device__ globals)
__device__ float g_z[BATCH * HWLO * CH];    // conv(x), channel-last  [b][hw][c]
__device__ float g_om[BATCH * HWLO * 12];   // [b][hw][ ox(4), oy(4), sigmoid(mask)(4) ]

// ---------------------------------------------------------------------------
// Kernel 1: fused 1x1 convs at LOW resolution.
//   outputs rows 0..63  -> conv_w @ x            -> g_z   (channel-last)
//   rows 64..71         -> offset_w @ x + b      -> g_om[0..7]
//   rows 72..75         -> sigmoid(mask_w@x + b) -> g_om[8..11]
// Tile: 64 pixels x 80 outputs, K=64. 320 threads, 4x4 microtiles.
// ---------------------------------------------------------------------------
__global__ __launch_bounds__(320) void conv_lowres_kernel(
    const float* __restrict__ x,
    const float* __restrict__ conv_w,
    const float* __restrict__ offset_w,
    const float* __restrict__ offset_b,
    const float* __restrict__ mask_w,
    const float* __restrict__ mask_b)
{
    __shared__ float Xs[64][64];   // [c][pix]
    __shared__ float Wt[64][80];   // [c][o]  (transposed weights)

    const int b = blockIdx.y;
    const int pix0 = blockIdx.x * 64;
    const int t = threadIdx.x;

    // Load weights transposed into smem
    for (int idx = t; idx < 64 * 80; idx += 320) {
        int c = idx / 80, o = idx % 80;
        float v;
        if (o < 64)      v = conv_w[o * 64 + c];
        else if (o < 72) v = offset_w[(o - 64) * 64 + c];
        else if (o < 76) v = mask_w[(o - 72) * 64 + c];
        else             v = 0.f;
        Wt[c][o] = v;
    }
    // Load x tile: x layout [b][c][hw]
    const float* xb = x + ((size_t)b * CH) * HWLO + pix0;
    for (int idx = t; idx < 64 * 64; idx += 320) {
        int c = idx >> 6, p = idx & 63;
        Xs[c][p] = xb[c * HWLO + p];
    }
    __syncthreads();

    const int tx = t % 20;        // output-block id (o = tx*4)
    const int ty = t / 20;        // pixel-block id  (p = ty*4)
    const int ob = tx * 4, pb = ty * 4;

    float acc[4][4];
    #pragma unroll
    for (int i = 0; i < 4; i++)
        #pragma unroll
        for (int j = 0; j < 4; j++) acc[i][j] = 0.f;

    #pragma unroll 4
    for (int c = 0; c < 64; c++) {
        float4 a = *reinterpret_cast<const float4*>(&Xs[c][pb]);
        float4 w = *reinterpret_cast<const float4*>(&Wt[c][ob]);
        float av[4] = {a.x, a.y, a.z, a.w};
        float wv[4] = {w.x, w.y, w.z, w.w};
        #pragma unroll
        for (int i = 0; i < 4; i++)
            #pragma unroll
            for (int j = 0; j < 4; j++)
                acc[i][j] += av[i] * wv[j];
    }

    const int pixbase = b * HWLO + pix0 + pb;
    if (ob < 64) {
        #pragma unroll
        for (int i = 0; i < 4; i++) {
            float4 v = make_float4(acc[i][0], acc[i][1], acc[i][2], acc[i][3]);
            *reinterpret_cast<float4*>(&g_z[(pixbase + i) * CH + ob]) = v;
        }
    } else if (ob < 72) {
        #pragma unroll
        for (int i = 0; i < 4; i++)
            #pragma unroll
            for (int j = 0; j < 4; j++)
                g_om[(pixbase + i) * 12 + (ob - 64) + j] = acc[i][j] + offset_b[ob - 64 + j];
    } else if (ob < 76) {
        #pragma unroll
        for (int i = 0; i < 4; i++)
            #pragma unroll
            for (int j = 0; j < 4; j++) {
                float v = acc[i][j] + mask_b[ob - 72 + j];
                g_om[(pixbase + i) * 12 + 8 + (ob - 72) + j] = 1.f / (1.f + __expf(-v));
            }
    }
}

// ---------------------------------------------------------------------------
// Composite (grid_sample o upsample) weights for one dimension:
// 2 grid-sample corners (zero-padded outside [0,160)) each bilinear over
// 2 low-res taps (edge-clamped) -> <=3 distinct low-res rows.
// ---------------------------------------------------------------------------
__device__ __forceinline__ void dim_weights(float coord, float w[3], int& rbase)
{
    w[0] = w[1] = w[2] = 0.f;
    int c0 = (int)floorf(coord);
    float f = coord - (float)c0;
    float cw0 = 1.f - f, cw1 = f;
    rbase = -1;
    #pragma unroll
    for (int k = 0; k < 2; k++) {
        int h = c0 + k;
        float cw = k ? cw1 : cw0;
        if (h < 0 || h >= HHI) continue;
        float cl = 0.5f * (float)h - 0.25f;
        cl = fminf(fmaxf(cl, 0.f), (float)(HLO - 1));
        int i0 = (int)cl;                   // cl >= 0
        float fw = cl - (float)i0;
        int i1 = min(i0 + 1, HLO - 1);
        if (rbase < 0) rbase = i0;
        int d = i0 - rbase;                 // 0 or 1
        w[d]               += cw * (1.f - fw);
        w[d + (i1 - i0)]   += cw * fw;
    }
    if (rbase < 0) rbase = 0;               // fully outside: all weights zero
}

// ---------------------------------------------------------------------------
// Kernel 2: fused grid-sample(upsample(z)) * mask, BN, SiLU, NCHW write.
// Block: 16 output pixels (one row segment) x 64 channels. 256 threads.
// ---------------------------------------------------------------------------
__global__ __launch_bounds__(256) void sample_kernel(
    float* __restrict__ out,
    const float* __restrict__ bn_gamma,
    const float* __restrict__ bn_beta,
    const float* __restrict__ bn_mean,
    const float* __restrict__ bn_var)
{
    __shared__ float s_wy[16][3];
    __shared__ float s_wx[16][3];
    __shared__ float s_m[16];
    __shared__ int   s_ry[16];
    __shared__ int   s_rx[16];
    __shared__ float s_bns[64];
    __shared__ float s_bnb[64];
    __shared__ float s_out[16 * 65];   // [pix][o], pad 65 -> conflict-free

    const int t = threadIdx.x;
    const int b = blockIdx.z;
    const int hs = blockIdx.y;
    const int ws0 = blockIdx.x * 16;

    if (t < 64) {
        float sc = bn_gamma[t] * rsqrtf(bn_var[t] + 1e-5f);
        s_bns[t] = sc;
        s_bnb[t] = bn_beta[t] - bn_mean[t] * sc;
    }
    if (t < 16) {
        int ws = ws0 + t;
        int h = hs >> 1, w = ws >> 1;
        int p = ((hs & 1) << 1) | (ws & 1);
        const float* om = g_om + ((b * HWLO + h * WLO + w) * 12);
        float ox = om[p];
        float oy = om[4 + p];
        s_m[t] = om[8 + p];
        float gx = -1.f + (float)ws * (2.f / (float)(WHI - 1)) + ox;
        float gy = -1.f + (float)hs * (2.f / (float)(HHI - 1)) + oy;
        float ix = ((gx + 1.f) * (float)WHI - 1.f) * 0.5f;
        float iy = ((gy + 1.f) * (float)HHI - 1.f) * 0.5f;
        float wy[3], wx[3]; int ry, rx;
        dim_weights(iy, wy, ry);
        dim_weights(ix, wx, rx);
        #pragma unroll
        for (int k = 0; k < 3; k++) { s_wy[t][k] = wy[k]; s_wx[t][k] = wx[k]; }
        s_ry[t] = ry; s_rx[t] = rx;
    }
    __syncthreads();

    const int pix = t >> 4;      // 0..15
    const int cg  = t & 15;      // channel group of 4
    const int ry = s_ry[pix], rx = s_rx[pix];
    float wy[3] = {s_wy[pix][0], s_wy[pix][1], s_wy[pix][2]};
    float wx[3] = {s_wx[pix][0], s_wx[pix][1], s_wx[pix][2]};
    const float m = s_m[pix];

    const float* zb = g_z + (size_t)b * HWLO * CH + cg * 4;
    float4 acc = make_float4(0.f, 0.f, 0.f, 0.f);
    #pragma unroll
    for (int i = 0; i < 3; i++) {
        int rr = min(ry + i, HLO - 1);
        const float* zrow = zb + rr * WLO * CH;
        #pragma unroll
        for (int j = 0; j < 3; j++) {
            int cc = min(rx + j, WLO - 1);
            float wgt = wy[i] * wx[j];
            float4 v = *reinterpret_cast<const float4*>(zrow + cc * CH);
            acc.x += wgt * v.x; acc.y += wgt * v.y;
            acc.z += wgt * v.z; acc.w += wgt * v.w;
        }
    }

    // mask, BN, SiLU
    float vals[4] = {acc.x * m, acc.y * m, acc.z * m, acc.w * m};
    #pragma unroll
    for (int k = 0; k < 4; k++) {
        int o = cg * 4 + k;
        float y = vals[k] * s_bns[o] + s_bnb[o];
        y = y / (1.f + __expf(-y));
        s_out[pix * 65 + o] = y;
    }
    __syncthreads();

    // Coalesced NCHW write: 16 consecutive ws per channel
    const size_t obase = (((size_t)b * CH) * HHI + hs) * WHI + ws0;
    #pragma unroll
    for (int k = 0; k < 4; k++) {
        int n = t + k * 256;
        int o = n >> 4, px = n & 15;
        out[obase + (size_t)o * (HHI * WHI) + px] = s_out[px * 65 + o];
    }
}

// ---------------------------------------------------------------------------
extern "C" void kernel_launch(void* const* d_in, const int* in_sizes, int n_in,
                              void* d_out, int out_size)
{
    const float* x        = (const float*)d_in[0];
    const float* offset_w = (const float*)d_in[1];
    const float* offset_b = (const float*)d_in[2];
    const float* mask_w   = (const float*)d_in[3];
    const float* mask_b   = (const float*)d_in[4];
    const float* conv_w   = (const float*)d_in[5];
    const float* bn_gamma = (const float*)d_in[6];
    const float* bn_beta  = (const float*)d_in[7];
    const float* bn_mean  = (const float*)d_in[8];
    const float* bn_var   = (const float*)d_in[9];
    float* out = (float*)d_out;

    conv_lowres_kernel<<<dim3(HWLO / 64, BATCH), 320>>>(
        x, conv_w, offset_w, offset_b, mask_w, mask_b);
    sample_kernel<<<dim3(WHI / 16, HHI, BATCH), 256>>>(
        out, bn_gamma, bn_beta, bn_mean, bn_var);
}

// round 2
// speedup vs baseline: 1.1497x; 1.1497x over previous
#include <cuda_runtime.h>
#include <math.h>

#define BATCH 16
#define CH 64
#define HLO 80
#define WLO 80
#define HWLO (HLO*WLO)
#define HHI 160
#define WHI 160

typedef unsigned long long ull;

// Scratch
__device__ float g_z[BATCH * HWLO * CH];    // conv(x), channel-last [b][hw][c]
__device__ float g_om[BATCH * HWLO * 12];   // [b][hw][ ox(4), oy(4), sig(mask)(4) ]

// ---- packed f32x2 helpers -------------------------------------------------
__device__ __forceinline__ ull fma2(ull a, ull b, ull c) {
    ull d;
    asm("fma.rn.f32x2 %0, %1, %2, %3;" : "=l"(d) : "l"(a), "l"(b), "l"(c));
    return d;
}
__device__ __forceinline__ ull packdup(float w) {
    ull d; unsigned u = __float_as_uint(w);
    asm("mov.b64 %0, {%1, %2};" : "=l"(d) : "r"(u), "r"(u));
    return d;
}
__device__ __forceinline__ float2 u2f2(ull v) {
    float2 r;
    asm("mov.b64 {%0, %1}, %2;" : "=f"(r.x), "=f"(r.y) : "l"(v));
    return r;
}

// ---------------------------------------------------------------------------
// Kernel 1: fused 1x1 convs at LOW resolution, f32x2 packed math.
// Tile: 128 pixels x 80 outputs, K=64 (two 32-chunks). 160 threads,
// 8x8 microtiles (pixels packed in f32x2 pairs).
//   outputs 0..63  -> conv_w @ x            -> g_z (channel-last)
//   64..71         -> offset_w @ x + b      -> g_om[0..7]
//   72..75         -> sigmoid(mask_w@x + b) -> g_om[8..11]
// ---------------------------------------------------------------------------
__global__ __launch_bounds__(160) void conv_lowres_kernel(
    const float* __restrict__ x,
    const float* __restrict__ conv_w,
    const float* __restrict__ offset_w,
    const float* __restrict__ offset_b,
    const float* __restrict__ mask_w,
    const float* __restrict__ mask_b)
{
    __shared__ float Xs[32][128];  // one K-chunk of inputs   (16 KB)
    __shared__ float Wt[64][80];   // all weights, transposed (20 KB)

    const int b = blockIdx.y;
    const int pix0 = blockIdx.x * 128;
    const int t = threadIdx.x;

    // Load all weights transposed (once)
    for (int idx = t; idx < 64 * 80; idx += 160) {
        int c = idx / 80, o = idx % 80;
        float v;
        if (o < 64)      v = conv_w[o * 64 + c];
        else if (o < 72) v = offset_w[(o - 64) * 64 + c];
        else if (o < 76) v = mask_w[(o - 72) * 64 + c];
        else             v = 0.f;
        Wt[c][o] = v;
    }

    const int tx = t % 10;         // output block: ob = tx*8
    const int ty = t / 10;         // pixel  block: pb = ty*8
    const int ob = tx * 8, pb = ty * 8;

    ull acc[8][4];                 // [o][pixel-pair]
    #pragma unroll
    for (int o = 0; o < 8; o++)
        #pragma unroll
        for (int p = 0; p < 4; p++) acc[o][p] = 0ull;

    const float* xb = x + ((size_t)b * CH) * HWLO + pix0;

    for (int kk = 0; kk < 64; kk += 32) {
        __syncthreads();
        // load X chunk [32 c][128 px] as float4
        for (int idx = t; idx < 32 * 32; idx += 160) {
            int c = idx >> 5, p4 = idx & 31;
            *reinterpret_cast<float4*>(&Xs[c][p4 * 4]) =
                *reinterpret_cast<const float4*>(&xb[(kk + c) * HWLO + p4 * 4]);
        }
        __syncthreads();

        #pragma unroll 4
        for (int c = 0; c < 32; c++) {
            ulonglong2 a01 = *reinterpret_cast<const ulonglong2*>(&Xs[c][pb]);
            ulonglong2 a23 = *reinterpret_cast<const ulonglong2*>(&Xs[c][pb + 4]);
            ull a[4] = {a01.x, a01.y, a23.x, a23.y};
            float4 w0 = *reinterpret_cast<const float4*>(&Wt[kk ? 32 + c : c][ob]);
            float4 w1 = *reinterpret_cast<const float4*>(&Wt[kk ? 32 + c : c][ob + 4]);
            ull wd[8] = {packdup(w0.x), packdup(w0.y), packdup(w0.z), packdup(w0.w),
                         packdup(w1.x), packdup(w1.y), packdup(w1.z), packdup(w1.w)};
            #pragma unroll
            for (int o = 0; o < 8; o++)
                #pragma unroll
                for (int p = 0; p < 4; p++)
                    acc[o][p] = fma2(a[p], wd[o], acc[o][p]);
        }
    }

    const int pixbase = b * HWLO + pix0 + pb;

    if (ob < 64) {
        #pragma unroll
        for (int i = 0; i < 8; i++) {
            float f[8];
            #pragma unroll
            for (int o = 0; o < 8; o++) {
                float2 v = u2f2(acc[o][i >> 1]);
                f[o] = (i & 1) ? v.y : v.x;
            }
            float* dst = &g_z[(size_t)(pixbase + i) * CH + ob];
            *reinterpret_cast<float4*>(dst)     = make_float4(f[0], f[1], f[2], f[3]);
            *reinterpret_cast<float4*>(dst + 4) = make_float4(f[4], f[5], f[6], f[7]);
        }
    } else if (ob == 64) {
        #pragma unroll
        for (int i = 0; i < 8; i++) {
            float f[8];
            #pragma unroll
            for (int o = 0; o < 8; o++) {
                float2 v = u2f2(acc[o][i >> 1]);
                f[o] = ((i & 1) ? v.y : v.x) + offset_b[o];
            }
            float* dst = &g_om[(size_t)(pixbase + i) * 12];
            *reinterpret_cast<float4*>(dst)     = make_float4(f[0], f[1], f[2], f[3]);
            *reinterpret_cast<float4*>(dst + 4) = make_float4(f[4], f[5], f[6], f[7]);
        }
    } else { // ob == 72: outputs 72..75 are mask; 76..79 are zero padding
        #pragma unroll
        for (int i = 0; i < 8; i++) {
            float f[4];
            #pragma unroll
            for (int o = 0; o < 4; o++) {
                float2 v = u2f2(acc[o][i >> 1]);
                float m = ((i & 1) ? v.y : v.x) + mask_b[o];
                f[o] = 1.f / (1.f + __expf(-m));
            }
            *reinterpret_cast<float4*>(&g_om[(size_t)(pixbase + i) * 12 + 8]) =
                make_float4(f[0], f[1], f[2], f[3]);
        }
    }
}

// ---------------------------------------------------------------------------
// Composite (grid_sample o upsample) weights for one dimension.
// ---------------------------------------------------------------------------
__device__ __forceinline__ void dim_weights(float coord, float w[3], int& rbase)
{
    w[0] = w[1] = w[2] = 0.f;
    int c0 = (int)floorf(coord);
    float f = coord - (float)c0;
    float cw0 = 1.f - f, cw1 = f;
    rbase = -1;
    #pragma unroll
    for (int k = 0; k < 2; k++) {
        int h = c0 + k;
        float cw = k ? cw1 : cw0;
        if (h < 0 || h >= HHI) continue;
        float cl = 0.5f * (float)h - 0.25f;
        cl = fminf(fmaxf(cl, 0.f), (float)(HLO - 1));
        int i0 = (int)cl;
        float fw = cl - (float)i0;
        int i1 = min(i0 + 1, HLO - 1);
        if (rbase < 0) rbase = i0;
        int d = i0 - rbase;
        w[d]             += cw * (1.f - fw);
        w[d + (i1 - i0)] += cw * fw;
    }
    if (rbase < 0) rbase = 0;
}

// ---------------------------------------------------------------------------
// Kernel 2: fused sampler. 16 output pixels x 64 channels per block.
// Taps precomputed as (element offset, weight); zero-weight taps skipped
// (no L1 traffic for predicated-off lanes).
// ---------------------------------------------------------------------------
__global__ __launch_bounds__(256) void sample_kernel(
    float* __restrict__ out,
    const float* __restrict__ bn_gamma,
    const float* __restrict__ bn_beta,
    const float* __restrict__ bn_mean,
    const float* __restrict__ bn_var)
{
    __shared__ float s_tw[16][9];
    __shared__ int   s_to[16][9];
    __shared__ float s_m[16];
    __shared__ float s_bns[64];
    __shared__ float s_bnb[64];
    __shared__ float s_out[16 * 65];

    const int t = threadIdx.x;
    const int b = blockIdx.z;
    const int hs = blockIdx.y;
    const int ws0 = blockIdx.x * 16;

    if (t < 64) {
        float sc = bn_gamma[t] * rsqrtf(bn_var[t] + 1e-5f);
        s_bns[t] = sc;
        s_bnb[t] = bn_beta[t] - bn_mean[t] * sc;
    }
    if (t < 16) {
        int ws = ws0 + t;
        int h = hs >> 1, w = ws >> 1;
        int p = ((hs & 1) << 1) | (ws & 1);
        const float* om = g_om + ((size_t)(b * HWLO + h * WLO + w) * 12);
        float ox = om[p];
        float oy = om[4 + p];
        s_m[t] = om[8 + p];
        float gx = -1.f + (float)ws * (2.f / (float)(WHI - 1)) + ox;
        float gy = -1.f + (float)hs * (2.f / (float)(HHI - 1)) + oy;
        float ix = ((gx + 1.f) * (float)WHI - 1.f) * 0.5f;
        float iy = ((gy + 1.f) * (float)HHI - 1.f) * 0.5f;
        float wy[3], wx[3]; int ry, rx;
        dim_weights(iy, wy, ry);
        dim_weights(ix, wx, rx);
        #pragma unroll
        for (int i = 0; i < 3; i++) {
            int rr = min(ry + i, HLO - 1);
            #pragma unroll
            for (int j = 0; j < 3; j++) {
                int cc = min(rx + j, WLO - 1);
                s_tw[t][i * 3 + j] = wy[i] * wx[j];
                s_to[t][i * 3 + j] = (rr * WLO + cc) * CH;
            }
        }
    }
    __syncthreads();

    const int pix = t >> 4;
    const int cg  = t & 15;
    const float* zb = g_z + (size_t)b * HWLO * CH + (cg << 2);

    float4 acc = make_float4(0.f, 0.f, 0.f, 0.f);
    #pragma unroll
    for (int k = 0; k < 9; k++) {
        float w = s_tw[pix][k];
        if (w != 0.f) {
            float4 v = *reinterpret_cast<const float4*>(zb + s_to[pix][k]);
            acc.x += w * v.x; acc.y += w * v.y;
            acc.z += w * v.z; acc.w += w * v.w;
        }
    }

    const float m = s_m[pix];
    float vals[4] = {acc.x * m, acc.y * m, acc.z * m, acc.w * m};
    #pragma unroll
    for (int k = 0; k < 4; k++) {
        int o = cg * 4 + k;
        float y = vals[k] * s_bns[o] + s_bnb[o];
        y = y / (1.f + __expf(-y));
        s_out[pix * 65 + o] = y;
    }
    __syncthreads();

    const size_t obase = (((size_t)b * CH) * HHI + hs) * WHI + ws0;
    #pragma unroll
    for (int k = 0; k < 4; k++) {
        int n = t + k * 256;
        int o = n >> 4, px = n & 15;
        out[obase + (size_t)o * (HHI * WHI) + px] = s_out[px * 65 + o];
    }
}

// ---------------------------------------------------------------------------
extern "C" void kernel_launch(void* const* d_in, const int* in_sizes, int n_in,
                              void* d_out, int out_size)
{
    const float* x        = (const float*)d_in[0];
    const float* offset_w = (const float*)d_in[1];
    const float* offset_b = (const float*)d_in[2];
    const float* mask_w   = (const float*)d_in[3];
    const float* mask_b   = (const float*)d_in[4];
    const float* conv_w   = (const float*)d_in[5];
    const float* bn_gamma = (const float*)d_in[6];
    const float* bn_beta  = (const float*)d_in[7];
    const float* bn_mean  = (const float*)d_in[8];
    const float* bn_var   = (const float*)d_in[9];
    float* out = (float*)d_out;

    conv_lowres_kernel<<<dim3(HWLO / 128, BATCH), 160>>>(
        x, conv_w, offset_w, offset_b, mask_w, mask_b);
    sample_kernel<<<dim3(WHI / 16, HHI, BATCH), 256>>>(
        out, bn_gamma, bn_beta, bn_mean, bn_var);
}

// round 3
// speedup vs baseline: 1.4934x; 1.2990x over previous
#include <cuda_runtime.h>
#include <cuda_fp16.h>
#include <math.h>

#define BATCH 16
#define CH 64
#define HLO 80
#define WLO 80
#define HWLO (HLO*WLO)
#define HHI 160
#define WHI 160

typedef unsigned long long ull;

// Scratch
__device__ __half g_zh[BATCH * HWLO * CH];  // conv(x), fp16, channel-last [b][hw][c]
__device__ float  g_om[BATCH * HWLO * 12];  // [b][hw][ ox(4), oy(4), sig(mask)(4) ]

struct alignas(16) H8 { __half2 h[4]; };

// ---- packed f32x2 helpers -------------------------------------------------
__device__ __forceinline__ ull fma2(ull a, ull b, ull c) {
    ull d;
    asm("fma.rn.f32x2 %0, %1, %2, %3;" : "=l"(d) : "l"(a), "l"(b), "l"(c));
    return d;
}
__device__ __forceinline__ ull packdup(float w) {
    ull d; unsigned u = __float_as_uint(w);
    asm("mov.b64 %0, {%1, %2};" : "=l"(d) : "r"(u), "r"(u));
    return d;
}
__device__ __forceinline__ float2 u2f2(ull v) {
    float2 r;
    asm("mov.b64 {%0, %1}, %2;" : "=f"(r.x), "=f"(r.y) : "l"(v));
    return r;
}

// ---------------------------------------------------------------------------
// Kernel 1: fused 1x1 convs at LOW resolution, f32x2 packed math.
// Tile: 128 pixels x 80 outputs, K=64 (fully smem-resident, single sync).
// 160 threads, 8x8 microtiles (pixels packed in f32x2 pairs).
// Dynamic smem: Xs[64][128] (32KB) + Wt[64][80] (20KB) = 52KB.
// ---------------------------------------------------------------------------
__global__ __launch_bounds__(160, 3) void conv_lowres_kernel(
    const float* __restrict__ x,
    const float* __restrict__ conv_w,
    const float* __restrict__ offset_w,
    const float* __restrict__ offset_b,
    const float* __restrict__ mask_w,
    const float* __restrict__ mask_b)
{
    extern __shared__ float smem[];
    float (*Xs)[128] = (float(*)[128])smem;              // [c][pix]
    float (*Wt)[80]  = (float(*)[80])(smem + 64 * 128);  // [c][o]

    const int b = blockIdx.y;
    const int pix0 = blockIdx.x * 128;
    const int t = threadIdx.x;

    // Load all weights transposed
    for (int idx = t; idx < 64 * 80; idx += 160) {
        int c = idx / 80, o = idx % 80;
        float v;
        if (o < 64)      v = conv_w[o * 64 + c];
        else if (o < 72) v = offset_w[(o - 64) * 64 + c];
        else if (o < 76) v = mask_w[(o - 72) * 64 + c];
        else             v = 0.f;
        Wt[c][o] = v;
    }
    // Load full X tile [64 c][128 px] as float4
    const float* xb = x + ((size_t)b * CH) * HWLO + pix0;
    for (int idx = t; idx < 64 * 32; idx += 160) {
        int c = idx >> 5, p4 = idx & 31;
        *reinterpret_cast<float4*>(&Xs[c][p4 * 4]) =
            *reinterpret_cast<const float4*>(&xb[c * HWLO + p4 * 4]);
    }
    __syncthreads();

    const int tx = t % 10;         // output block: ob = tx*8
    const int ty = t / 10;         // pixel  block: pb = ty*8
    const int ob = tx * 8, pb = ty * 8;

    ull acc[8][4];
    #pragma unroll
    for (int o = 0; o < 8; o++)
        #pragma unroll
        for (int p = 0; p < 4; p++) acc[o][p] = 0ull;

    #pragma unroll 8
    for (int c = 0; c < 64; c++) {
        ulonglong2 a01 = *reinterpret_cast<const ulonglong2*>(&Xs[c][pb]);
        ulonglong2 a23 = *reinterpret_cast<const ulonglong2*>(&Xs[c][pb + 4]);
        ull a[4] = {a01.x, a01.y, a23.x, a23.y};
        float4 w0 = *reinterpret_cast<const float4*>(&Wt[c][ob]);
        float4 w1 = *reinterpret_cast<const float4*>(&Wt[c][ob + 4]);
        ull wd[8] = {packdup(w0.x), packdup(w0.y), packdup(w0.z), packdup(w0.w),
                     packdup(w1.x), packdup(w1.y), packdup(w1.z), packdup(w1.w)};
        #pragma unroll
        for (int o = 0; o < 8; o++)
            #pragma unroll
            for (int p = 0; p < 4; p++)
                acc[o][p] = fma2(a[p], wd[o], acc[o][p]);
    }

    const int pixbase = b * HWLO + pix0 + pb;

    if (ob < 64) {
        #pragma unroll
        for (int i = 0; i < 8; i++) {
            float f[8];
            #pragma unroll
            for (int o = 0; o < 8; o++) {
                float2 v = u2f2(acc[o][i >> 1]);
                f[o] = (i & 1) ? v.y : v.x;
            }
            H8 hv;
            hv.h[0] = __floats2half2_rn(f[0], f[1]);
            hv.h[1] = __floats2half2_rn(f[2], f[3]);
            hv.h[2] = __floats2half2_rn(f[4], f[5]);
            hv.h[3] = __floats2half2_rn(f[6], f[7]);
            *reinterpret_cast<H8*>(&g_zh[(size_t)(pixbase + i) * CH + ob]) = hv;
        }
    } else if (ob == 64) {
        #pragma unroll
        for (int i = 0; i < 8; i++) {
            float f[8];
            #pragma unroll
            for (int o = 0; o < 8; o++) {
                float2 v = u2f2(acc[o][i >> 1]);
                f[o] = ((i & 1) ? v.y : v.x) + offset_b[o];
            }
            float* dst = &g_om[(size_t)(pixbase + i) * 12];
            *reinterpret_cast<float4*>(dst)     = make_float4(f[0], f[1], f[2], f[3]);
            *reinterpret_cast<float4*>(dst + 4) = make_float4(f[4], f[5], f[6], f[7]);
        }
    } else { // ob == 72: mask outputs 72..75 (76..79 zero pad)
        #pragma unroll
        for (int i = 0; i < 8; i++) {
            float f[4];
            #pragma unroll
            for (int o = 0; o < 4; o++) {
                float2 v = u2f2(acc[o][i >> 1]);
                float m = ((i & 1) ? v.y : v.x) + mask_b[o];
                f[o] = __fdividef(1.f, 1.f + __expf(-m));
            }
            *reinterpret_cast<float4*>(&g_om[(size_t)(pixbase + i) * 12 + 8]) =
                make_float4(f[0], f[1], f[2], f[3]);
        }
    }
}

// ---------------------------------------------------------------------------
// Composite (grid_sample o upsample) weights for one dimension.
// ---------------------------------------------------------------------------
__device__ __forceinline__ void dim_weights(float coord, float w[3], int& rbase)
{
    w[0] = w[1] = w[2] = 0.f;
    int c0 = (int)floorf(coord);
    float f = coord - (float)c0;
    float cw0 = 1.f - f, cw1 = f;
    rbase = -1;
    #pragma unroll
    for (int k = 0; k < 2; k++) {
        int h = c0 + k;
        float cw = k ? cw1 : cw0;
        if (h < 0 || h >= HHI) continue;
        float cl = 0.5f * (float)h - 0.25f;
        cl = fminf(fmaxf(cl, 0.f), (float)(HLO - 1));
        int i0 = (int)cl;
        float fw = cl - (float)i0;
        int i1 = min(i0 + 1, HLO - 1);
        if (rbase < 0) rbase = i0;
        int d = i0 - rbase;
        w[d]             += cw * (1.f - fw);
        w[d + (i1 - i0)] += cw * fw;
    }
    if (rbase < 0) rbase = 0;
}

// ---------------------------------------------------------------------------
// Kernel 2: fused sampler, fp16 z. 32 output pixels x 64 channels per block.
// Thread = 1 pixel x 8 channels; 9 unconditional batched uint4 gathers.
// ---------------------------------------------------------------------------
__global__ __launch_bounds__(256) void sample_kernel(
    float* __restrict__ out,
    const float* __restrict__ bn_gamma,
    const float* __restrict__ bn_beta,
    const float* __restrict__ bn_mean,
    const float* __restrict__ bn_var)
{
    __shared__ float s_tw[32][9];
    __shared__ int   s_to[32][9];
    __shared__ float s_m[32];
    __shared__ float s_bns[64];
    __shared__ float s_bnb[64];
    __shared__ float s_out[64 * 33];   // [o][px], stride 33

    const int t = threadIdx.x;
    const int b = blockIdx.z;
    const int hs = blockIdx.y;
    const int ws0 = blockIdx.x * 32;

    if (t < 64) {
        float sc = bn_gamma[t] * rsqrtf(bn_var[t] + 1e-5f);
        s_bns[t] = sc;
        s_bnb[t] = bn_beta[t] - bn_mean[t] * sc;
    }
    if (t < 32) {
        int ws = ws0 + t;
        int h = hs >> 1, w = ws >> 1;
        int p = ((hs & 1) << 1) | (ws & 1);
        const float* om = g_om + ((size_t)(b * HWLO + h * WLO + w) * 12);
        float ox = om[p];
        float oy = om[4 + p];
        s_m[t] = om[8 + p];
        float gx = -1.f + (float)ws * (2.f / (float)(WHI - 1)) + ox;
        float gy = -1.f + (float)hs * (2.f / (float)(HHI - 1)) + oy;
        float ix = ((gx + 1.f) * (float)WHI - 1.f) * 0.5f;
        float iy = ((gy + 1.f) * (float)HHI - 1.f) * 0.5f;
        float wy[3], wx[3]; int ry, rx;
        dim_weights(iy, wy, ry);
        dim_weights(ix, wx, rx);
        #pragma unroll
        for (int i = 0; i < 3; i++) {
            int rr = min(ry + i, HLO - 1);
            #pragma unroll
            for (int j = 0; j < 3; j++) {
                int cc = min(rx + j, WLO - 1);
                s_tw[t][i * 3 + j] = wy[i] * wx[j];
                s_to[t][i * 3 + j] = (rr * WLO + cc) * CH;
            }
        }
    }
    __syncthreads();

    const int px = t >> 3;             // 0..31
    const int c0 = (t & 7) * 8;        // channel base (8 channels/thread)
    const __half* zb = g_zh + (size_t)b * HWLO * CH + c0;

    float acc[8];
    #pragma unroll
    for (int j = 0; j < 8; j++) acc[j] = 0.f;

    #pragma unroll
    for (int k = 0; k < 9; k++) {
        float wgt = s_tw[px][k];
        uint4 v = *reinterpret_cast<const uint4*>(zb + s_to[px][k]);
        float2 f0 = __half22float2(*reinterpret_cast<const __half2*>(&v.x));
        float2 f1 = __half22float2(*reinterpret_cast<const __half2*>(&v.y));
        float2 f2 = __half22float2(*reinterpret_cast<const __half2*>(&v.z));
        float2 f3 = __half22float2(*reinterpret_cast<const __half2*>(&v.w));
        acc[0] = fmaf(wgt, f0.x, acc[0]);
        acc[1] = fmaf(wgt, f0.y, acc[1]);
        acc[2] = fmaf(wgt, f1.x, acc[2]);
        acc[3] = fmaf(wgt, f1.y, acc[3]);
        acc[4] = fmaf(wgt, f2.x, acc[4]);
        acc[5] = fmaf(wgt, f2.y, acc[5]);
        acc[6] = fmaf(wgt, f3.x, acc[6]);
        acc[7] = fmaf(wgt, f3.y, acc[7]);
    }

    const float m = s_m[px];
    #pragma unroll
    for (int j = 0; j < 8; j++) {
        int o = c0 + j;
        float y = acc[j] * (m * s_bns[o]) + s_bnb[o];
        y = y * __fdividef(1.f, 1.f + __expf(-y));   // SiLU
        s_out[o * 33 + px] = y;
    }
    __syncthreads();

    // Coalesced NCHW writes: out[b][o][hs][ws0 + px]
    #pragma unroll
    for (int r = 0; r < 2; r++) {
        int idx = t + r * 256;
        int o = idx >> 3, px0 = (idx & 7) * 4;
        float4 v = make_float4(s_out[o * 33 + px0],     s_out[o * 33 + px0 + 1],
                               s_out[o * 33 + px0 + 2], s_out[o * 33 + px0 + 3]);
        *reinterpret_cast<float4*>(
            out + (((size_t)(b * CH + o)) * HHI + hs) * WHI + ws0 + px0) = v;
    }
}

// ---------------------------------------------------------------------------
extern "C" void kernel_launch(void* const* d_in, const int* in_sizes, int n_in,
                              void* d_out, int out_size)
{
    const float* x        = (const float*)d_in[0];
    const float* offset_w = (const float*)d_in[1];
    const float* offset_b = (const float*)d_in[2];
    const float* mask_w   = (const float*)d_in[3];
    const float* mask_b   = (const float*)d_in[4];
    const float* conv_w   = (const float*)d_in[5];
    const float* bn_gamma = (const float*)d_in[6];
    const float* bn_beta  = (const float*)d_in[7];
    const float* bn_mean  = (const float*)d_in[8];
    const float* bn_var   = (const float*)d_in[9];
    float* out = (float*)d_out;

    const int conv_smem = (64 * 128 + 64 * 80) * sizeof(float);  // 53248
    cudaFuncSetAttribute(conv_lowres_kernel,
                         cudaFuncAttributeMaxDynamicSharedMemorySize, conv_smem);

    conv_lowres_kernel<<<dim3(HWLO / 128, BATCH), 160, conv_smem>>>(
        x, conv_w, offset_w, offset_b, mask_w, mask_b);
    sample_kernel<<<dim3(WHI / 32, HHI, BATCH), 256>>>(
        out, bn_gamma, bn_beta, bn_mean, bn_var);
}